// round 7
// baseline (speedup 1.0000x reference)
#include <cuda_runtime.h>
#include <cuda_fp16.h>

#define NN 50000
#define NE 1600000
#define H1_BLOCKS ((NN + 255) / 256)              // 196
#define SCAN_BLK 1024
#define N_SBLK ((NN + SCAN_BLK - 1) / SCAN_BLK)   // 49

// Scratch (device globals — zero-initialized at load; kernels self-clean so
// every graph replay starts from identical state; no allocation anywhere)
__device__ __align__(16) __half g_h1h[NN * 32];
__device__ __align__(16) __half g_h2h[NN * 64];           // fp16 (self term)
__device__ __align__(16) unsigned short g_h2q[NN * 32];   // e4m3 x2 (gathers)
__device__ int g_cnt[NN];                 // zeroed by k_scanB after use
__device__ int g_rank[NE];
__device__ int g_rowptr[NN + 1];
__device__ int g_bsum[N_SBLK];
__device__ unsigned long long g_csr[NE];  // packed {col, weight fp32 bits}
__device__ float g_pool[64];              // zeroed by last l2 block
__device__ unsigned g_tick;               // l2 ticket (self-reset)

__device__ __forceinline__ float lrelu(float v) { return v > 0.f ? v : 0.01f * v; }

// ---- manual e4m3 conversion (no cuda_fp8.h dependency) --------------------
__device__ __forceinline__ unsigned f_to_e4m3(float f) {
    float a = fabsf(f);
    unsigned s = (__float_as_uint(f) >> 24) & 0x80u;
    if (a >= 448.f) return s | 0x7eu;                 // clamp to max finite
    if (a < 0.015625f) {                              // subnormal: m = round(a*512)
        unsigned m = (unsigned)(fmaf(a, 512.f, 0.5f));
        return s | (m > 8u ? 8u : m);                 // m==8 encodes 2^-6 exactly
    }
    unsigned u = __float_as_uint(a);
    int e = (int)((u >> 23) & 0xffu) - 127 + 7;       // e4m3 biased exp (>=1 here)
    unsigned m = (u >> 20) & 7u;
    unsigned rem = u & 0xfffffu;
    unsigned val = ((unsigned)e << 3) | m;
    if (rem > 0x80000u || (rem == 0x80000u && (m & 1u))) val++;  // RNE, carry ok
    if (val > 0x7eu) val = 0x7eu;
    return s | val;
}
__device__ __forceinline__ float e4m3_to_f(unsigned v) {
    unsigned s = (v & 0x80u) << 24;
    unsigned e = (v >> 3) & 0xfu;
    unsigned m = v & 7u;
    if (e == 0) {
        float f = (float)m * 0.001953125f;            // m * 2^-9
        return __uint_as_float(s | __float_as_uint(f));
    }
    return __uint_as_float(s | ((e + 120u) << 23) | (m << 20));
}

// ---------------------------------------------------------------------------
// Fused: blocks [0,H1_BLOCKS) compute h1 = x @ W1^T -> fp16
//        blocks [H1_BLOCKS,..) histogram rows + record per-edge rank
// ---------------------------------------------------------------------------
__global__ void __launch_bounds__(256) k_h1hist(const float* __restrict__ x,
                                                const float* __restrict__ W1,
                                                const int* __restrict__ edge, int E) {
    const int tid = threadIdx.x;
    if (blockIdx.x < H1_BLOCKS) {
        __shared__ float W1s[32 * 20];
        __shared__ float xs[256 * 21];
        for (int i = tid; i < 32 * 20; i += 256) W1s[i] = W1[i];
        const int base = blockIdx.x * 256;
        for (int i = tid; i < 256 * 20; i += 256) {
            int gi = base * 20 + i;
            int n = i / 20, k = i % 20;
            xs[n * 21 + k] = (gi < NN * 20) ? x[gi] : 0.f;
        }
        __syncthreads();
        const int n = base + tid;
        if (n >= NN) return;
        float xr[20];
#pragma unroll
        for (int k = 0; k < 20; k++) xr[k] = xs[tid * 21 + k];
#pragma unroll
        for (int j = 0; j < 32; j += 4) {
            float a0 = 0.f, a1 = 0.f, a2 = 0.f, a3 = 0.f;
#pragma unroll
            for (int k = 0; k < 20; k++) {
                a0 = fmaf(xr[k], W1s[(j + 0) * 20 + k], a0);
                a1 = fmaf(xr[k], W1s[(j + 1) * 20 + k], a1);
                a2 = fmaf(xr[k], W1s[(j + 2) * 20 + k], a2);
                a3 = fmaf(xr[k], W1s[(j + 3) * 20 + k], a3);
            }
            *reinterpret_cast<__half2*>(g_h1h + n * 32 + j)     = __floats2half2_rn(a0, a1);
            *reinterpret_cast<__half2*>(g_h1h + n * 32 + j + 2) = __floats2half2_rn(a2, a3);
        }
    } else {
        int i = (blockIdx.x - H1_BLOCKS) * 256 + tid;
        if (i < E) g_rank[i] = atomicAdd(&g_cnt[__ldg(edge + i)], 1);
    }
}

// ---------------------------------------------------------------------------
// Scan pass A: block-local exclusive prefix into g_rowptr, block sums to g_bsum
// ---------------------------------------------------------------------------
__global__ void __launch_bounds__(SCAN_BLK) k_scanA() {
    __shared__ int wsum[32];
    const int tid = threadIdx.x, lane = tid & 31, wid = tid >> 5;
    const int i = blockIdx.x * SCAN_BLK + tid;
    int v = (i < NN) ? g_cnt[i] : 0;
    int incl = v;
#pragma unroll
    for (int off = 1; off < 32; off <<= 1) {
        int t = __shfl_up_sync(0xffffffffu, incl, off);
        if (lane >= off) incl += t;
    }
    if (lane == 31) wsum[wid] = incl;
    __syncthreads();
    if (wid == 0) {
        int s = wsum[lane];
#pragma unroll
        for (int off = 1; off < 32; off <<= 1) {
            int t = __shfl_up_sync(0xffffffffu, s, off);
            if (lane >= off) s += t;
        }
        wsum[lane] = s;
    }
    __syncthreads();
    int woff = (wid > 0) ? wsum[wid - 1] : 0;
    if (i < NN) g_rowptr[i] = woff + incl - v;         // block-local exclusive
    if (tid == SCAN_BLK - 1) g_bsum[blockIdx.x] = woff + incl;
}

// ---------------------------------------------------------------------------
// Scan pass B: add prefix of earlier block sums (<=49, trivial), zero g_cnt.
// ---------------------------------------------------------------------------
__global__ void __launch_bounds__(SCAN_BLK) k_scanB() {
    __shared__ int sOff;
    const int tid = threadIdx.x;
    const int b = blockIdx.x;
    if (tid == 0) {
        int off = 0;
        for (int p = 0; p < b; p++) off += __ldg(&g_bsum[p]);
        sOff = off;
        if (b == N_SBLK - 1) g_rowptr[NN] = off + __ldg(&g_bsum[b]);
    }
    __syncthreads();
    const int i = b * SCAN_BLK + tid;
    if (i < NN) {
        g_rowptr[i] += sOff;
        g_cnt[i] = 0;                                   // self-clean for replay
    }
}

// ---------------------------------------------------------------------------
// Scatter edges into CSR slots (atomic-free). 4 edges/thread for MLP.
// ---------------------------------------------------------------------------
__global__ void __launch_bounds__(256) k_scatter(const int* __restrict__ edge,
                                                 const float* __restrict__ weight, int E) {
    const int T = gridDim.x * blockDim.x;
    const int e0 = blockIdx.x * blockDim.x + threadIdx.x;
    int r[4], c[4], rk[4];
    float w[4];
    int pos[4];
    bool ok[4];
#pragma unroll
    for (int u = 0; u < 4; u++) {
        int e = e0 + u * T;
        ok[u] = (e < E);
        if (ok[u]) {
            r[u] = __ldg(edge + e);
            c[u] = __ldg(edge + E + e);
            w[u] = __ldg(weight + e);
            rk[u] = __ldg(g_rank + e);
        }
    }
#pragma unroll
    for (int u = 0; u < 4; u++)
        if (ok[u]) pos[u] = __ldg(&g_rowptr[r[u]]) + rk[u];
#pragma unroll
    for (int u = 0; u < 4; u++)
        if (ok[u])
            g_csr[pos[u]] = (unsigned long long)(unsigned)c[u] |
                            ((unsigned long long)__float_as_uint(w[u]) << 32);
}

// ---------------------------------------------------------------------------
// Layer 1 (CSR, warp/node) fused with W3 GEMM.
// Lane computes cols (2*lane, 2*lane+1) -> packed half2 + fp8x2 stores.
// ---------------------------------------------------------------------------
__global__ void __launch_bounds__(256) k_l1(const float* __restrict__ b1,
                                            const float* __restrict__ W3) {
    __shared__ float2 W3s2[32 * 32];   // [k][j2] = (W3[2j2][k], W3[2j2+1][k])
    const int tid = threadIdx.x;       // 8 warps
    for (int i = tid; i < 32 * 32; i += 256) {
        int j2 = i & 31, k = i >> 5;
        W3s2[k * 32 + j2] = make_float2(W3[(2 * j2) * 32 + k], W3[(2 * j2 + 1) * 32 + k]);
    }
    __syncthreads();
    const int wid = tid >> 5, lane = tid & 31;
    const int n = blockIdx.x * 8 + wid;
    if (n >= NN) return;
    const int start = g_rowptr[n], end = g_rowptr[n + 1];
    const float bl = __ldg(b1 + lane);
    float acc = 0.f;
    int i = start;
    for (; i + 8 <= end; i += 8) {
        unsigned long long e[8];
#pragma unroll
        for (int u = 0; u < 8; u++) e[u] = __ldg(g_csr + i + u);
        float h[8];
#pragma unroll
        for (int u = 0; u < 8; u++)
            h[u] = __half2float(__ldg(g_h1h + (int)(unsigned)e[u] * 32 + lane));
#pragma unroll
        for (int u = 0; u < 8; u++)
            acc += lrelu(fmaf(__uint_as_float((unsigned)(e[u] >> 32)), h[u], bl));
    }
    for (; i < end; i++) {
        unsigned long long e0 = __ldg(g_csr + i);
        float h0 = __half2float(__ldg(g_h1h + (int)(unsigned)e0 * 32 + lane));
        acc += lrelu(fmaf(__uint_as_float((unsigned)(e0 >> 32)), h0, bl));
    }
    float deg = fmaxf((float)(end - start), 1.f);
    float out1 = acc / deg + lrelu(__half2float(g_h1h[n * 32 + lane]) + bl);
    float a0 = 0.f, a1 = 0.f;
#pragma unroll
    for (int k = 0; k < 32; k++) {
        float ov = __shfl_sync(0xffffffffu, out1, k);
        float2 wv = W3s2[k * 32 + lane];
        a0 = fmaf(ov, wv.x, a0);
        a1 = fmaf(ov, wv.y, a1);
    }
    *reinterpret_cast<__half2*>(g_h2h + n * 64 + lane * 2) = __floats2half2_rn(a0, a1);
    g_h2q[n * 32 + lane] = (unsigned short)(f_to_e4m3(a0) | (f_to_e4m3(a1) << 8));
}

// ---------------------------------------------------------------------------
// Layer 2: fp8 gathers + fp16 self term + global mean pool + classifier.
// Self-cleans g_pool and g_tick for graph replay. No spin loops.
// ---------------------------------------------------------------------------
__global__ void __launch_bounds__(256) k_l2(const float* __restrict__ b3,
                                            const float* __restrict__ W7,
                                            const float* __restrict__ b7,
                                            float* __restrict__ out) {
    __shared__ float sp[8][64];
    __shared__ bool sLast;
    const int tid = threadIdx.x;     // 8 warps
    const int wid = tid >> 5, lane = tid & 31;
    const int n = blockIdx.x * 8 + wid;
    float ox = 0.f, oy = 0.f;
    if (n < NN) {
        const int start = g_rowptr[n], end = g_rowptr[n + 1];
        const float2 bl = __ldg(reinterpret_cast<const float2*>(b3) + lane);
        float ax = 0.f, ay = 0.f;
        int i = start;
        for (; i + 8 <= end; i += 8) {
            unsigned long long e[8];
#pragma unroll
            for (int u = 0; u < 8; u++) e[u] = __ldg(g_csr + i + u);
            unsigned q[8];
#pragma unroll
            for (int u = 0; u < 8; u++)
                q[u] = __ldg(g_h2q + (int)(unsigned)e[u] * 32 + lane);
#pragma unroll
            for (int u = 0; u < 8; u++) {
                float hx = e4m3_to_f(q[u] & 0xffu);
                float hy = e4m3_to_f(q[u] >> 8);
                float w = __uint_as_float((unsigned)(e[u] >> 32));
                ax += lrelu(fmaf(w, hx, bl.x));
                ay += lrelu(fmaf(w, hy, bl.y));
            }
        }
        for (; i < end; i++) {
            unsigned long long e0 = __ldg(g_csr + i);
            unsigned q0 = __ldg(g_h2q + (int)(unsigned)e0 * 32 + lane);
            float w0 = __uint_as_float((unsigned)(e0 >> 32));
            ax += lrelu(fmaf(w0, e4m3_to_f(q0 & 0xffu), bl.x));
            ay += lrelu(fmaf(w0, e4m3_to_f(q0 >> 8), bl.y));
        }
        float deg = fmaxf((float)(end - start), 1.f);
        float2 hs = __half22float2(*reinterpret_cast<const __half2*>(g_h2h + n * 64 + lane * 2));
        ox = ax / deg + lrelu(hs.x + bl.x);
        oy = ay / deg + lrelu(hs.y + bl.y);
    }
    sp[wid][lane * 2] = ox;
    sp[wid][lane * 2 + 1] = oy;
    __syncthreads();
    if (tid < 64) {
        float s = 0.f;
#pragma unroll
        for (int w = 0; w < 8; w++) s += sp[w][tid];
        atomicAdd(&g_pool[tid], s);
    }
    __syncthreads();
    if (tid == 0) {
        __threadfence();
        unsigned t = atomicAdd(&g_tick, 1u);
        sLast = (t == gridDim.x - 1);
    }
    __syncthreads();
    if (!sLast) return;
    if (tid == 0) {
        __threadfence();
        const float inv = 1.f / (float)NN;
        float l0 = b7[0], l1 = b7[1];
#pragma unroll
        for (int j = 0; j < 64; j++) {
            float p = g_pool[j] * inv;
            l0 = fmaf(p, W7[j], l0);
            l1 = fmaf(p, W7[64 + j], l1);
        }
        float m = fmaxf(l0, l1);
        float lse = m + logf(expf(l0 - m) + expf(l1 - m));
        out[0] = l0 - lse;
        out[1] = l1 - lse;
    }
    __syncthreads();
    if (tid < 64) g_pool[tid] = 0.f;
    if (tid == 0) g_tick = 0u;
}

extern "C" void kernel_launch(void* const* d_in, const int* in_sizes, int n_in,
                              void* d_out, int out_size) {
    const float* x      = (const float*)d_in[0];
    const int*   edge   = (const int*)d_in[1];
    const float* weight = (const float*)d_in[2];
    const float* W1     = (const float*)d_in[3];
    const float* b1     = (const float*)d_in[4];
    const float* W3     = (const float*)d_in[5];
    const float* b3     = (const float*)d_in[6];
    const float* W7     = (const float*)d_in[7];
    const float* b7     = (const float*)d_in[8];
    const int E = in_sizes[2];

    const int histBlocks = (E + 255) / 256;
    k_h1hist<<<H1_BLOCKS + histBlocks, 256>>>(x, W1, edge, E);
    k_scanA<<<N_SBLK, SCAN_BLK>>>();
    k_scanB<<<N_SBLK, SCAN_BLK>>>();
    k_scatter<<<(E / 4 + 255) / 256, 256>>>(edge, weight, E);
    k_l1<<<(NN + 7) / 8, 256>>>(b1, W3);
    k_l2<<<(NN + 7) / 8, 256>>>(b3, W7, b7, (float*)d_out);
}

// round 9
// speedup vs baseline: 1.1263x; 1.1263x over previous
#include <cuda_runtime.h>
#include <cuda_fp16.h>

#define NN 50000
#define NE 1600000
#define H1_BLOCKS ((NN + 255) / 256)              // 196
#define SCAN_BLK 1024
#define N_SBLK ((NN + SCAN_BLK - 1) / SCAN_BLK)   // 49

// Scratch (device globals — zero-initialized at load; kernels self-clean so
// every graph replay starts from identical state; no allocation anywhere)
__device__ __align__(16) __half g_h1h[NN * 32];           // fp16 (self term)
__device__ __align__(16) unsigned char g_h1q[NN * 32];    // e4m3 (gathers)
__device__ __align__(16) __half g_h2h[NN * 64];           // fp16 (self term)
__device__ __align__(16) unsigned short g_h2q[NN * 32];   // e4m3 x2 (gathers)
__device__ int g_cnt[NN];                 // zeroed by k_scanB after use
__device__ int g_rank[NE];
__device__ int g_rowptr[NN + 1];
__device__ int g_bsum[N_SBLK];
__device__ unsigned long long g_csr[NE];  // packed {col, weight fp32 bits}
__device__ float g_pool[64];              // zeroed by last l2 block
__device__ unsigned g_tick;               // l2 ticket (self-reset)

__device__ __forceinline__ float lrelu(float v) { return v > 0.f ? v : 0.01f * v; }

// ---- e4m3 encode (RNE, runs only NN*48 times — cost irrelevant) -----------
__device__ __forceinline__ unsigned f_to_e4m3(float f) {
    float a = fabsf(f);
    unsigned s = (__float_as_uint(f) >> 24) & 0x80u;
    if (a >= 448.f) return s | 0x7eu;
    if (a < 0.015625f) {
        unsigned m = (unsigned)(fmaf(a, 512.f, 0.5f));
        return s | (m > 8u ? 8u : m);
    }
    unsigned u = __float_as_uint(a);
    int e = (int)((u >> 23) & 0xffu) - 127 + 7;
    unsigned m = (u >> 20) & 7u;
    unsigned rem = u & 0xfffffu;
    unsigned val = ((unsigned)e << 3) | m;
    if (rem > 0x80000u || (rem == 0x80000u && (m & 1u))) val++;
    if (val > 0x7eu) val = 0x7eu;
    return s | val;
}

// ---- e4m3 decode, branchless, value scaled by 2^-8 (fold 256 into weight) --
__device__ __forceinline__ float e4m3_f_s(unsigned b) {   // returns true/256
    unsigned t = ((b & 0x80u) << 8) | ((b & 0x7fu) << 7);
    __half_raw hr; hr.x = (unsigned short)t;
    return __half2float(*reinterpret_cast<const __half*>(&hr));
}
__device__ __forceinline__ float2 e4m3x2_f_s(unsigned q) { // pair, each /256
    unsigned t = ((q & 0x80u) << 8) | ((q & 0x7fu) << 7)
               | ((q & 0x8000u) << 16) | ((q & 0x7f00u) << 15);
    __half2_raw hr; hr.x = (unsigned short)(t & 0xffffu);
    hr.y = (unsigned short)(t >> 16);
    return __half22float2(*reinterpret_cast<const __half2*>(&hr));
}

// ---------------------------------------------------------------------------
// Fused: blocks [0,H1_BLOCKS) compute h1 = x @ W1^T -> fp16 + e4m3
//        blocks [H1_BLOCKS,..) histogram rows + record per-edge rank
// ---------------------------------------------------------------------------
__global__ void __launch_bounds__(256) k_h1hist(const float* __restrict__ x,
                                                const float* __restrict__ W1,
                                                const int* __restrict__ edge, int E) {
    const int tid = threadIdx.x;
    if (blockIdx.x < H1_BLOCKS) {
        __shared__ float W1s[32 * 20];
        __shared__ float xs[256 * 21];
        for (int i = tid; i < 32 * 20; i += 256) W1s[i] = W1[i];
        const int base = blockIdx.x * 256;
        for (int i = tid; i < 256 * 20; i += 256) {
            int gi = base * 20 + i;
            int n = i / 20, k = i % 20;
            xs[n * 21 + k] = (gi < NN * 20) ? x[gi] : 0.f;
        }
        __syncthreads();
        const int n = base + tid;
        if (n >= NN) return;
        float xr[20];
#pragma unroll
        for (int k = 0; k < 20; k++) xr[k] = xs[tid * 21 + k];
#pragma unroll
        for (int j = 0; j < 32; j += 4) {
            float a0 = 0.f, a1 = 0.f, a2 = 0.f, a3 = 0.f;
#pragma unroll
            for (int k = 0; k < 20; k++) {
                a0 = fmaf(xr[k], W1s[(j + 0) * 20 + k], a0);
                a1 = fmaf(xr[k], W1s[(j + 1) * 20 + k], a1);
                a2 = fmaf(xr[k], W1s[(j + 2) * 20 + k], a2);
                a3 = fmaf(xr[k], W1s[(j + 3) * 20 + k], a3);
            }
            *reinterpret_cast<__half2*>(g_h1h + n * 32 + j)     = __floats2half2_rn(a0, a1);
            *reinterpret_cast<__half2*>(g_h1h + n * 32 + j + 2) = __floats2half2_rn(a2, a3);
            unsigned q = f_to_e4m3(a0) | (f_to_e4m3(a1) << 8)
                       | (f_to_e4m3(a2) << 16) | (f_to_e4m3(a3) << 24);
            *reinterpret_cast<unsigned*>(g_h1q + n * 32 + j) = q;
        }
    } else {
        int i = (blockIdx.x - H1_BLOCKS) * 256 + tid;
        if (i < E) g_rank[i] = atomicAdd(&g_cnt[__ldg(edge + i)], 1);
    }
}

// ---------------------------------------------------------------------------
// Scan pass A: block-local exclusive prefix into g_rowptr, block sums to g_bsum
// ---------------------------------------------------------------------------
__global__ void __launch_bounds__(SCAN_BLK) k_scanA() {
    __shared__ int wsum[32];
    const int tid = threadIdx.x, lane = tid & 31, wid = tid >> 5;
    const int i = blockIdx.x * SCAN_BLK + tid;
    int v = (i < NN) ? g_cnt[i] : 0;
    int incl = v;
#pragma unroll
    for (int off = 1; off < 32; off <<= 1) {
        int t = __shfl_up_sync(0xffffffffu, incl, off);
        if (lane >= off) incl += t;
    }
    if (lane == 31) wsum[wid] = incl;
    __syncthreads();
    if (wid == 0) {
        int s = wsum[lane];
#pragma unroll
        for (int off = 1; off < 32; off <<= 1) {
            int t = __shfl_up_sync(0xffffffffu, s, off);
            if (lane >= off) s += t;
        }
        wsum[lane] = s;
    }
    __syncthreads();
    int woff = (wid > 0) ? wsum[wid - 1] : 0;
    if (i < NN) g_rowptr[i] = woff + incl - v;
    if (tid == SCAN_BLK - 1) g_bsum[blockIdx.x] = woff + incl;
}

// ---------------------------------------------------------------------------
// Scan pass B: add prefix of earlier block sums (<=49, trivial), zero g_cnt.
// ---------------------------------------------------------------------------
__global__ void __launch_bounds__(SCAN_BLK) k_scanB() {
    __shared__ int sOff;
    const int tid = threadIdx.x;
    const int b = blockIdx.x;
    if (tid == 0) {
        int off = 0;
        for (int p = 0; p < b; p++) off += __ldg(&g_bsum[p]);
        sOff = off;
        if (b == N_SBLK - 1) g_rowptr[NN] = off + __ldg(&g_bsum[b]);
    }
    __syncthreads();
    const int i = b * SCAN_BLK + tid;
    if (i < NN) {
        g_rowptr[i] += sOff;
        g_cnt[i] = 0;
    }
}

// ---------------------------------------------------------------------------
// Scatter edges into CSR slots (atomic-free: rowptr[r] + rank[e])
// ---------------------------------------------------------------------------
__global__ void k_scatter(const int* __restrict__ edge, const float* __restrict__ weight, int E) {
    int e = blockIdx.x * blockDim.x + threadIdx.x;
    if (e >= E) return;
    int r = __ldg(edge + e);
    int c = __ldg(edge + E + e);
    float w = __ldg(weight + e);
    int pos = __ldg(&g_rowptr[r]) + g_rank[e];
    g_csr[pos] = (unsigned long long)(unsigned)c |
                 ((unsigned long long)__float_as_uint(w) << 32);
}

// ---------------------------------------------------------------------------
// Layer 1 (CSR, warp/node): e4m3 gathers + fp16 self term, fused W3 GEMM.
// Lane computes cols (2*lane, 2*lane+1); packed half2 + fp8x2 stores.
// ---------------------------------------------------------------------------
__global__ void __launch_bounds__(256) k_l1(const float* __restrict__ b1,
                                            const float* __restrict__ W3) {
    __shared__ float2 W3s2[32 * 32];   // [k][j2] = (W3[2j2][k], W3[2j2+1][k])
    const int tid = threadIdx.x;       // 8 warps
    for (int i = tid; i < 32 * 32; i += 256) {
        int j2 = i & 31, k = i >> 5;
        W3s2[k * 32 + j2] = make_float2(W3[(2 * j2) * 32 + k], W3[(2 * j2 + 1) * 32 + k]);
    }
    __syncthreads();
    const int wid = tid >> 5, lane = tid & 31;
    const int n = blockIdx.x * 8 + wid;
    if (n >= NN) return;
    const int start = g_rowptr[n], end = g_rowptr[n + 1];
    const float bl = __ldg(b1 + lane);
    float acc = 0.f;
    int i = start;
    for (; i + 8 <= end; i += 8) {
        unsigned long long e[8];
#pragma unroll
        for (int u = 0; u < 8; u++) e[u] = __ldg(g_csr + i + u);
        unsigned q[8];
#pragma unroll
        for (int u = 0; u < 8; u++)
            q[u] = __ldg(g_h1q + (int)(unsigned)e[u] * 32 + lane);
#pragma unroll
        for (int u = 0; u < 8; u++) {
            float w256 = __uint_as_float((unsigned)(e[u] >> 32)) * 256.f;
            acc += lrelu(fmaf(w256, e4m3_f_s(q[u]), bl));
        }
    }
    for (; i < end; i++) {
        unsigned long long e0 = __ldg(g_csr + i);
        unsigned q0 = __ldg(g_h1q + (int)(unsigned)e0 * 32 + lane);
        float w256 = __uint_as_float((unsigned)(e0 >> 32)) * 256.f;
        acc += lrelu(fmaf(w256, e4m3_f_s(q0), bl));
    }
    float deg = fmaxf((float)(end - start), 1.f);
    float out1 = acc / deg + lrelu(__half2float(g_h1h[n * 32 + lane]) + bl);
    float a0 = 0.f, a1 = 0.f;
#pragma unroll
    for (int k = 0; k < 32; k++) {
        float ov = __shfl_sync(0xffffffffu, out1, k);
        float2 wv = W3s2[k * 32 + lane];
        a0 = fmaf(ov, wv.x, a0);
        a1 = fmaf(ov, wv.y, a1);
    }
    *reinterpret_cast<__half2*>(g_h2h + n * 64 + lane * 2) = __floats2half2_rn(a0, a1);
    g_h2q[n * 32 + lane] = (unsigned short)(f_to_e4m3(a0) | (f_to_e4m3(a1) << 8));
}

// ---------------------------------------------------------------------------
// Layer 2: e4m3 gathers + fp16 self term + global mean pool + classifier.
// Self-cleans g_pool and g_tick for graph replay. No spin loops.
// ---------------------------------------------------------------------------
__global__ void __launch_bounds__(256) k_l2(const float* __restrict__ b3,
                                            const float* __restrict__ W7,
                                            const float* __restrict__ b7,
                                            float* __restrict__ out) {
    __shared__ float sp[8][64];
    __shared__ bool sLast;
    const int tid = threadIdx.x;     // 8 warps
    const int wid = tid >> 5, lane = tid & 31;
    const int n = blockIdx.x * 8 + wid;
    float ox = 0.f, oy = 0.f;
    if (n < NN) {
        const int start = g_rowptr[n], end = g_rowptr[n + 1];
        const float2 bl = __ldg(reinterpret_cast<const float2*>(b3) + lane);
        float ax = 0.f, ay = 0.f;
        int i = start;
        for (; i + 8 <= end; i += 8) {
            unsigned long long e[8];
#pragma unroll
            for (int u = 0; u < 8; u++) e[u] = __ldg(g_csr + i + u);
            unsigned q[8];
#pragma unroll
            for (int u = 0; u < 8; u++)
                q[u] = __ldg(g_h2q + (int)(unsigned)e[u] * 32 + lane);
#pragma unroll
            for (int u = 0; u < 8; u++) {
                float2 h = e4m3x2_f_s(q[u]);
                float w256 = __uint_as_float((unsigned)(e[u] >> 32)) * 256.f;
                ax += lrelu(fmaf(w256, h.x, bl.x));
                ay += lrelu(fmaf(w256, h.y, bl.y));
            }
        }
        for (; i < end; i++) {
            unsigned long long e0 = __ldg(g_csr + i);
            unsigned q0 = __ldg(g_h2q + (int)(unsigned)e0 * 32 + lane);
            float2 h0 = e4m3x2_f_s(q0);
            float w256 = __uint_as_float((unsigned)(e0 >> 32)) * 256.f;
            ax += lrelu(fmaf(w256, h0.x, bl.x));
            ay += lrelu(fmaf(w256, h0.y, bl.y));
        }
        float deg = fmaxf((float)(end - start), 1.f);
        float2 hs = __half22float2(*reinterpret_cast<const __half2*>(g_h2h + n * 64 + lane * 2));
        ox = ax / deg + lrelu(hs.x + bl.x);
        oy = ay / deg + lrelu(hs.y + bl.y);
    }
    sp[wid][lane * 2] = ox;
    sp[wid][lane * 2 + 1] = oy;
    __syncthreads();
    if (tid < 64) {
        float s = 0.f;
#pragma unroll
        for (int w = 0; w < 8; w++) s += sp[w][tid];
        atomicAdd(&g_pool[tid], s);
    }
    __syncthreads();
    if (tid == 0) {
        __threadfence();
        unsigned t = atomicAdd(&g_tick, 1u);
        sLast = (t == gridDim.x - 1);
    }
    __syncthreads();
    if (!sLast) return;
    if (tid == 0) {
        __threadfence();
        const float inv = 1.f / (float)NN;
        float l0 = b7[0], l1 = b7[1];
#pragma unroll
        for (int j = 0; j < 64; j++) {
            float p = g_pool[j] * inv;
            l0 = fmaf(p, W7[j], l0);
            l1 = fmaf(p, W7[64 + j], l1);
        }
        float m = fmaxf(l0, l1);
        float lse = m + logf(expf(l0 - m) + expf(l1 - m));
        out[0] = l0 - lse;
        out[1] = l1 - lse;
    }
    __syncthreads();
    if (tid < 64) g_pool[tid] = 0.f;
    if (tid == 0) g_tick = 0u;
}

extern "C" void kernel_launch(void* const* d_in, const int* in_sizes, int n_in,
                              void* d_out, int out_size) {
    const float* x      = (const float*)d_in[0];
    const int*   edge   = (const int*)d_in[1];
    const float* weight = (const float*)d_in[2];
    const float* W1     = (const float*)d_in[3];
    const float* b1     = (const float*)d_in[4];
    const float* W3     = (const float*)d_in[5];
    const float* b3     = (const float*)d_in[6];
    const float* W7     = (const float*)d_in[7];
    const float* b7     = (const float*)d_in[8];
    const int E = in_sizes[2];

    const int histBlocks = (E + 255) / 256;
    k_h1hist<<<H1_BLOCKS + histBlocks, 256>>>(x, W1, edge, E);
    k_scanA<<<N_SBLK, SCAN_BLK>>>();
    k_scanB<<<N_SBLK, SCAN_BLK>>>();
    k_scatter<<<(E + 255) / 256, 256>>>(edge, weight, E);
    k_l1<<<(NN + 7) / 8, 256>>>(b1, W3);
    k_l2<<<(NN + 7) / 8, 256>>>(b3, W7, b7, (float*)d_out);
}

// round 10
// speedup vs baseline: 1.3136x; 1.1662x over previous
#include <cuda_runtime.h>
#include <cuda_fp16.h>

#define NN 50000
#define NE 1600000
#define H1_BLOCKS ((NN + 255) / 256)              // 196
#define SCAN_BLK 1024
#define N_SBLK ((NN + SCAN_BLK - 1) / SCAN_BLK)   // 49

// Scratch (device globals — zero-initialized at load; kernels self-clean so
// every graph replay starts from identical state; no allocation anywhere)
__device__ __align__(16) __half g_h1h[NN * 32];
__device__ __align__(16) __half g_h2h[NN * 64];
__device__ int g_cnt[NN];                 // zeroed by k_scanB after use
__device__ int g_rank[NE];
__device__ int g_rowptr[NN + 1];
__device__ int g_bsum[N_SBLK];
__device__ unsigned g_csr[NE];            // packed {w:fp16 hi16, col:16 lo}
__device__ float g_pool[64];              // zeroed by last l2 block
__device__ unsigned g_tick;               // l2 ticket (self-reset)

__device__ __forceinline__ float lrelu(float v) { return v > 0.f ? v : 0.01f * v; }

__device__ __forceinline__ float csr_w(unsigned v) {
    __half_raw hr; hr.x = (unsigned short)(v >> 16);
    return __half2float(*reinterpret_cast<const __half*>(&hr));
}

// ---------------------------------------------------------------------------
// Fused: blocks [0,H1_BLOCKS) compute h1 = x @ W1^T -> fp16
//        blocks [H1_BLOCKS,..) histogram rows + record per-edge rank
// ---------------------------------------------------------------------------
__global__ void __launch_bounds__(256) k_h1hist(const float* __restrict__ x,
                                                const float* __restrict__ W1,
                                                const int* __restrict__ edge, int E) {
    const int tid = threadIdx.x;
    if (blockIdx.x < H1_BLOCKS) {
        __shared__ float W1s[32 * 20];
        __shared__ float xs[256 * 21];
        for (int i = tid; i < 32 * 20; i += 256) W1s[i] = W1[i];
        const int base = blockIdx.x * 256;
        for (int i = tid; i < 256 * 20; i += 256) {
            int gi = base * 20 + i;
            int n = i / 20, k = i % 20;
            xs[n * 21 + k] = (gi < NN * 20) ? x[gi] : 0.f;
        }
        __syncthreads();
        const int n = base + tid;
        if (n >= NN) return;
        float xr[20];
#pragma unroll
        for (int k = 0; k < 20; k++) xr[k] = xs[tid * 21 + k];
#pragma unroll
        for (int j = 0; j < 32; j += 4) {
            float a0 = 0.f, a1 = 0.f, a2 = 0.f, a3 = 0.f;
#pragma unroll
            for (int k = 0; k < 20; k++) {
                a0 = fmaf(xr[k], W1s[(j + 0) * 20 + k], a0);
                a1 = fmaf(xr[k], W1s[(j + 1) * 20 + k], a1);
                a2 = fmaf(xr[k], W1s[(j + 2) * 20 + k], a2);
                a3 = fmaf(xr[k], W1s[(j + 3) * 20 + k], a3);
            }
            *reinterpret_cast<__half2*>(g_h1h + n * 32 + j)     = __floats2half2_rn(a0, a1);
            *reinterpret_cast<__half2*>(g_h1h + n * 32 + j + 2) = __floats2half2_rn(a2, a3);
        }
    } else {
        int i = (blockIdx.x - H1_BLOCKS) * 256 + tid;
        if (i < E) g_rank[i] = atomicAdd(&g_cnt[__ldg(edge + i)], 1);
    }
}

// ---------------------------------------------------------------------------
// Scan pass A: block-local exclusive prefix into g_rowptr, block sums to g_bsum
// ---------------------------------------------------------------------------
__global__ void __launch_bounds__(SCAN_BLK) k_scanA() {
    __shared__ int wsum[32];
    const int tid = threadIdx.x, lane = tid & 31, wid = tid >> 5;
    const int i = blockIdx.x * SCAN_BLK + tid;
    int v = (i < NN) ? g_cnt[i] : 0;
    int incl = v;
#pragma unroll
    for (int off = 1; off < 32; off <<= 1) {
        int t = __shfl_up_sync(0xffffffffu, incl, off);
        if (lane >= off) incl += t;
    }
    if (lane == 31) wsum[wid] = incl;
    __syncthreads();
    if (wid == 0) {
        int s = wsum[lane];
#pragma unroll
        for (int off = 1; off < 32; off <<= 1) {
            int t = __shfl_up_sync(0xffffffffu, s, off);
            if (lane >= off) s += t;
        }
        wsum[lane] = s;
    }
    __syncthreads();
    int woff = (wid > 0) ? wsum[wid - 1] : 0;
    if (i < NN) g_rowptr[i] = woff + incl - v;
    if (tid == SCAN_BLK - 1) g_bsum[blockIdx.x] = woff + incl;
}

// ---------------------------------------------------------------------------
// Scan pass B: add prefix of earlier block sums (<=49, trivial), zero g_cnt.
// ---------------------------------------------------------------------------
__global__ void __launch_bounds__(SCAN_BLK) k_scanB() {
    __shared__ int sOff;
    const int tid = threadIdx.x;
    const int b = blockIdx.x;
    if (tid == 0) {
        int off = 0;
        for (int p = 0; p < b; p++) off += __ldg(&g_bsum[p]);
        sOff = off;
        if (b == N_SBLK - 1) g_rowptr[NN] = off + __ldg(&g_bsum[b]);
    }
    __syncthreads();
    const int i = b * SCAN_BLK + tid;
    if (i < NN) {
        g_rowptr[i] += sOff;
        g_cnt[i] = 0;
    }
}

// ---------------------------------------------------------------------------
// Scatter edges into packed CSR slots (atomic-free: rowptr[r] + rank[e])
// ---------------------------------------------------------------------------
__global__ void k_scatter(const int* __restrict__ edge, const float* __restrict__ weight, int E) {
    int e = blockIdx.x * blockDim.x + threadIdx.x;
    if (e >= E) return;
    int r = __ldg(edge + e);
    int c = __ldg(edge + E + e);
    float w = __ldg(weight + e);
    int pos = __ldg(&g_rowptr[r]) + g_rank[e];
    __half hw = __float2half_rn(w);
    unsigned short hb = *reinterpret_cast<unsigned short*>(&hw);
    g_csr[pos] = (unsigned)c | ((unsigned)hb << 16);
}

// ---------------------------------------------------------------------------
// Layer 1 (CSR, warp/node) fused with W3 GEMM. Unroll 16 for MLP.
// Lane computes cols (2*lane, 2*lane+1); packed half2 store.
// ---------------------------------------------------------------------------
__global__ void __launch_bounds__(256) k_l1(const float* __restrict__ b1,
                                            const float* __restrict__ W3) {
    __shared__ float2 W3s2[32 * 32];   // [k][j2] = (W3[2j2][k], W3[2j2+1][k])
    const int tid = threadIdx.x;       // 8 warps
    for (int i = tid; i < 32 * 32; i += 256) {
        int j2 = i & 31, k = i >> 5;
        W3s2[k * 32 + j2] = make_float2(W3[(2 * j2) * 32 + k], W3[(2 * j2 + 1) * 32 + k]);
    }
    __syncthreads();
    const int wid = tid >> 5, lane = tid & 31;
    const int n = blockIdx.x * 8 + wid;
    if (n >= NN) return;
    const int start = g_rowptr[n], end = g_rowptr[n + 1];
    const float bl = __ldg(b1 + lane);
    float acc = 0.f;
    int i = start;
    for (; i + 16 <= end; i += 16) {
        unsigned e[16];
#pragma unroll
        for (int u = 0; u < 16; u++) e[u] = __ldg(g_csr + i + u);
        __half h[16];
#pragma unroll
        for (int u = 0; u < 16; u++)
            h[u] = __ldg(g_h1h + (int)(e[u] & 0xffffu) * 32 + lane);
#pragma unroll
        for (int u = 0; u < 16; u++)
            acc += lrelu(fmaf(csr_w(e[u]), __half2float(h[u]), bl));
    }
    for (; i < end; i++) {
        unsigned e0 = __ldg(g_csr + i);
        __half h0 = __ldg(g_h1h + (int)(e0 & 0xffffu) * 32 + lane);
        acc += lrelu(fmaf(csr_w(e0), __half2float(h0), bl));
    }
    float deg = fmaxf((float)(end - start), 1.f);
    float out1 = acc / deg + lrelu(__half2float(g_h1h[n * 32 + lane]) + bl);
    float a0 = 0.f, a1 = 0.f;
#pragma unroll
    for (int k = 0; k < 32; k++) {
        float ov = __shfl_sync(0xffffffffu, out1, k);
        float2 wv = W3s2[k * 32 + lane];
        a0 = fmaf(ov, wv.x, a0);
        a1 = fmaf(ov, wv.y, a1);
    }
    *reinterpret_cast<__half2*>(g_h2h + n * 64 + lane * 2) = __floats2half2_rn(a0, a1);
}

// ---------------------------------------------------------------------------
// Layer 2 (CSR, warp/node) + global mean pool + (last block) classifier.
// Unroll 16. Self-cleans g_pool and g_tick for graph replay. No spin loops.
// ---------------------------------------------------------------------------
__global__ void __launch_bounds__(256) k_l2(const float* __restrict__ b3,
                                            const float* __restrict__ W7,
                                            const float* __restrict__ b7,
                                            float* __restrict__ out) {
    __shared__ float sp[8][64];
    __shared__ bool sLast;
    const int tid = threadIdx.x;     // 8 warps
    const int wid = tid >> 5, lane = tid & 31;
    const int n = blockIdx.x * 8 + wid;
    float ox = 0.f, oy = 0.f;
    if (n < NN) {
        const int start = g_rowptr[n], end = g_rowptr[n + 1];
        const float2 bl = __ldg(reinterpret_cast<const float2*>(b3) + lane);
        float ax = 0.f, ay = 0.f;
        int i = start;
        for (; i + 16 <= end; i += 16) {
            unsigned e[16];
#pragma unroll
            for (int u = 0; u < 16; u++) e[u] = __ldg(g_csr + i + u);
            __half2 h[16];
#pragma unroll
            for (int u = 0; u < 16; u++)
                h[u] = __ldg(reinterpret_cast<const __half2*>(
                           g_h2h + (int)(e[u] & 0xffffu) * 64 + lane * 2));
#pragma unroll
            for (int u = 0; u < 16; u++) {
                float2 hf = __half22float2(h[u]);
                float w = csr_w(e[u]);
                ax += lrelu(fmaf(w, hf.x, bl.x));
                ay += lrelu(fmaf(w, hf.y, bl.y));
            }
        }
        for (; i < end; i++) {
            unsigned e0 = __ldg(g_csr + i);
            float2 h0 = __half22float2(__ldg(reinterpret_cast<const __half2*>(
                            g_h2h + (int)(e0 & 0xffffu) * 64 + lane * 2)));
            float w0 = csr_w(e0);
            ax += lrelu(fmaf(w0, h0.x, bl.x));
            ay += lrelu(fmaf(w0, h0.y, bl.y));
        }
        float deg = fmaxf((float)(end - start), 1.f);
        float2 hs = __half22float2(*reinterpret_cast<const __half2*>(g_h2h + n * 64 + lane * 2));
        ox = ax / deg + lrelu(hs.x + bl.x);
        oy = ay / deg + lrelu(hs.y + bl.y);
    }
    sp[wid][lane * 2] = ox;
    sp[wid][lane * 2 + 1] = oy;
    __syncthreads();
    if (tid < 64) {
        float s = 0.f;
#pragma unroll
        for (int w = 0; w < 8; w++) s += sp[w][tid];
        atomicAdd(&g_pool[tid], s);
    }
    __syncthreads();
    if (tid == 0) {
        __threadfence();
        unsigned t = atomicAdd(&g_tick, 1u);
        sLast = (t == gridDim.x - 1);
    }
    __syncthreads();
    if (!sLast) return;
    if (tid == 0) {
        __threadfence();
        const float inv = 1.f / (float)NN;
        float l0 = b7[0], l1 = b7[1];
#pragma unroll
        for (int j = 0; j < 64; j++) {
            float p = g_pool[j] * inv;
            l0 = fmaf(p, W7[j], l0);
            l1 = fmaf(p, W7[64 + j], l1);
        }
        float m = fmaxf(l0, l1);
        float lse = m + logf(expf(l0 - m) + expf(l1 - m));
        out[0] = l0 - lse;
        out[1] = l1 - lse;
    }
    __syncthreads();
    if (tid < 64) g_pool[tid] = 0.f;
    if (tid == 0) g_tick = 0u;
}

extern "C" void kernel_launch(void* const* d_in, const int* in_sizes, int n_in,
                              void* d_out, int out_size) {
    const float* x      = (const float*)d_in[0];
    const int*   edge   = (const int*)d_in[1];
    const float* weight = (const float*)d_in[2];
    const float* W1     = (const float*)d_in[3];
    const float* b1     = (const float*)d_in[4];
    const float* W3     = (const float*)d_in[5];
    const float* b3     = (const float*)d_in[6];
    const float* W7     = (const float*)d_in[7];
    const float* b7     = (const float*)d_in[8];
    const int E = in_sizes[2];

    const int histBlocks = (E + 255) / 256;
    k_h1hist<<<H1_BLOCKS + histBlocks, 256>>>(x, W1, edge, E);
    k_scanA<<<N_SBLK, SCAN_BLK>>>();
    k_scanB<<<N_SBLK, SCAN_BLK>>>();
    k_scatter<<<(E + 255) / 256, 256>>>(edge, weight, E);
    k_l1<<<(NN + 7) / 8, 256>>>(b1, W3);
    k_l2<<<(NN + 7) / 8, 256>>>(b3, W7, b7, (float*)d_out);
}